// round 1
// baseline (speedup 1.0000x reference)
#include <cuda_runtime.h>
#include <math.h>

#define BATCH 4
#define SEQ   2048
#define EMB   512
#define NH    8
#define HD    64
#define MROWS (BATCH*SEQ)   // 8192

// Scratch (device globals: allocation-free per harness rules)
__device__ float g_Q[BATCH*NH*SEQ*HD];   // (b,h,n,d)
__device__ float g_K[BATCH*NH*SEQ*HD];
__device__ float g_V[BATCH*NH*SEQ*HD];
__device__ float g_AO[BATCH*SEQ*EMB];    // (b,n,e) attention output

// ---------------------------------------------------------------------------
// GEMM: C[m,e] = sum_k A[m,k] * W[e,k]   (A: MROWS x EMB row-major, W: EMB x EMB row-major)
// mode 0/1/2: write to g_Q/g_K/g_V in (b,h,n,d) layout (Q also could be scaled later)
// mode 3:     write plain row-major to dout
// Tile: BM=BN=64, BK=16, 256 threads, 4x4 micro-tile per thread.
// ---------------------------------------------------------------------------
__global__ __launch_bounds__(256) void gemm_nt(const float* __restrict__ A,
                                               const float* __restrict__ W,
                                               float* __restrict__ dout,
                                               int mode)
{
    __shared__ float Xs[16 * 68];   // Xs[k][m], pad 68 keeps float4 alignment
    __shared__ float Ws[16 * 68];   // Ws[k][e]

    const float* Ap = A ? A : g_AO;

    const int m0 = blockIdx.y * 64;
    const int e0 = blockIdx.x * 64;
    const int tid = threadIdx.x;
    const int tx = tid & 15;
    const int ty = tid >> 4;

    const int mm = tid >> 2;        // 0..63 : row within tile for loading
    const int k4 = (tid & 3) * 4;   // 0,4,8,12

    float acc[4][4] = {};

    for (int k0 = 0; k0 < EMB; k0 += 16) {
        float4 xa = *(const float4*)&Ap[(size_t)(m0 + mm) * EMB + k0 + k4];
        float4 wa = *(const float4*)&W [(size_t)(e0 + mm) * EMB + k0 + k4];
        __syncthreads();   // previous compute done before overwriting smem
        Xs[(k4 + 0) * 68 + mm] = xa.x;
        Xs[(k4 + 1) * 68 + mm] = xa.y;
        Xs[(k4 + 2) * 68 + mm] = xa.z;
        Xs[(k4 + 3) * 68 + mm] = xa.w;
        Ws[(k4 + 0) * 68 + mm] = wa.x;
        Ws[(k4 + 1) * 68 + mm] = wa.y;
        Ws[(k4 + 2) * 68 + mm] = wa.z;
        Ws[(k4 + 3) * 68 + mm] = wa.w;
        __syncthreads();
        #pragma unroll
        for (int k = 0; k < 16; k++) {
            float4 av = *(const float4*)&Xs[k * 68 + ty * 4];
            float4 bv = *(const float4*)&Ws[k * 68 + tx * 4];
            float a[4] = {av.x, av.y, av.z, av.w};
            float b[4] = {bv.x, bv.y, bv.z, bv.w};
            #pragma unroll
            for (int i = 0; i < 4; i++)
                #pragma unroll
                for (int j = 0; j < 4; j++)
                    acc[i][j] += a[i] * b[j];
        }
    }

    if (mode == 3) {
        #pragma unroll
        for (int i = 0; i < 4; i++) {
            int m = m0 + ty * 4 + i;
            float4 v = make_float4(acc[i][0], acc[i][1], acc[i][2], acc[i][3]);
            *(float4*)&dout[(size_t)m * EMB + e0 + tx * 4] = v;
        }
    } else {
        float* dst = (mode == 0) ? g_Q : (mode == 1) ? g_K : g_V;
        const int h = e0 >> 6;   // whole 64-wide e-tile lies inside one head
        #pragma unroll
        for (int i = 0; i < 4; i++) {
            int m = m0 + ty * 4 + i;
            int b = m >> 11;          // /SEQ
            int n = m & (SEQ - 1);
            float4 v = make_float4(acc[i][0], acc[i][1], acc[i][2], acc[i][3]);
            *(float4*)&dst[((size_t)(b * NH + h) * SEQ + n) * HD + tx * 4] = v;
        }
    }
}

// ---------------------------------------------------------------------------
// Causal flash attention, fp32. One CTA = one (b,h) x 64 query rows.
// Smem layouts (pad 68):
//   Qs[d][r]  (transposed, pre-scaled)    Ks[d][c] (transposed)
//   Vs[c][d]  (natural)                   Ps[c][r] (S/P transposed)
// ---------------------------------------------------------------------------
__global__ __launch_bounds__(256) void attn_kernel()
{
    extern __shared__ float sm[];
    float* Qs  = sm;
    float* Ks  = sm + 64 * 68;
    float* Vs  = sm + 2 * 64 * 68;
    float* Ps  = sm + 3 * 64 * 68;
    float* m_s = sm + 4 * 64 * 68;        // [64]
    float* l_s = m_s + 64;                // [64]
    float* a_s = l_s + 64;                // [64] rescale alpha

    const int bh = blockIdx.x;            // 0..31
    const int q0 = blockIdx.y * 64;
    const int tid = threadIdx.x;
    const int tx = tid & 15;
    const int ty = tid >> 4;

    const float* Qg = g_Q + (size_t)bh * SEQ * HD;
    const float* Kg = g_K + (size_t)bh * SEQ * HD;
    const float* Vg = g_V + (size_t)bh * SEQ * HD;

    // Load Q tile transposed, fold in softmax scale 1/sqrt(64) = 0.125
    #pragma unroll
    for (int i = 0; i < 16; i++) {
        int idx = tid + i * 256;          // 0..4095
        int r = idx >> 6, d = idx & 63;
        Qs[d * 68 + r] = Qg[(size_t)(q0 + r) * HD + d] * 0.125f;
    }
    if (tid < 64) { m_s[tid] = -1e30f; l_s[tid] = 0.0f; }

    float acc[4][4] = {};

    const int ktiles = (q0 >> 6) + 1;     // causal: only tiles with k0 <= q0
    for (int kt = 0; kt < ktiles; kt++) {
        const int k0 = kt * 64;
        __syncthreads();                  // prior PV done / Q load visible
        #pragma unroll
        for (int i = 0; i < 16; i++) {
            int idx = tid + i * 256;
            int c = idx >> 6, d = idx & 63;
            Ks[d * 68 + c] = Kg[(size_t)(k0 + c) * HD + d];
            Vs[c * 68 + d] = Vg[(size_t)(k0 + c) * HD + d];
        }
        __syncthreads();

        // S = Q K^T  (4x4 per thread)
        float s[4][4] = {};
        #pragma unroll
        for (int d = 0; d < 64; d++) {
            float4 av = *(const float4*)&Qs[d * 68 + ty * 4];
            float4 bv = *(const float4*)&Ks[d * 68 + tx * 4];
            float a[4] = {av.x, av.y, av.z, av.w};
            float b[4] = {bv.x, bv.y, bv.z, bv.w};
            #pragma unroll
            for (int i = 0; i < 4; i++)
                #pragma unroll
                for (int j = 0; j < 4; j++)
                    s[i][j] += a[i] * b[j];
        }

        // causal mask (only the diagonal tile can mask)
        if (kt == ktiles - 1) {
            #pragma unroll
            for (int i = 0; i < 4; i++)
                #pragma unroll
                for (int j = 0; j < 4; j++)
                    if (k0 + tx * 4 + j > q0 + ty * 4 + i) s[i][j] = -1e30f;
        }

        // store S transposed: Ps[col][row]
        #pragma unroll
        for (int i = 0; i < 4; i++)
            #pragma unroll
            for (int j = 0; j < 4; j++)
                Ps[(tx * 4 + j) * 68 + (ty * 4 + i)] = s[i][j];
        __syncthreads();

        // online softmax row pass: one thread per row
        if (tid < 64) {
            const int r = tid;
            float mo = m_s[r];
            float tm = -1e30f;
            #pragma unroll 8
            for (int j = 0; j < 64; j++) tm = fmaxf(tm, Ps[j * 68 + r]);
            float mn = fmaxf(mo, tm);
            float alpha = __expf(mo - mn);
            float lsum = 0.0f;
            #pragma unroll 8
            for (int j = 0; j < 64; j++) {
                float p = __expf(Ps[j * 68 + r] - mn);
                Ps[j * 68 + r] = p;
                lsum += p;
            }
            m_s[r] = mn;
            l_s[r] = l_s[r] * alpha + lsum;
            a_s[r] = alpha;
        }
        __syncthreads();

        // rescale accumulator, then O += P V
        float alr[4];
        #pragma unroll
        for (int i = 0; i < 4; i++) alr[i] = a_s[ty * 4 + i];
        #pragma unroll
        for (int i = 0; i < 4; i++)
            #pragma unroll
            for (int j = 0; j < 4; j++)
                acc[i][j] *= alr[i];

        #pragma unroll
        for (int jj = 0; jj < 64; jj++) {
            float4 av = *(const float4*)&Ps[jj * 68 + ty * 4];
            float4 bv = *(const float4*)&Vs[jj * 68 + tx * 4];
            float a[4] = {av.x, av.y, av.z, av.w};
            float b[4] = {bv.x, bv.y, bv.z, bv.w};
            #pragma unroll
            for (int i = 0; i < 4; i++)
                #pragma unroll
                for (int j = 0; j < 4; j++)
                    acc[i][j] += a[i] * b[j];
        }
    }

    // write O / l  to g_AO in (b, n, h*64+d) layout
    const int b = bh >> 3, h = bh & 7;
    #pragma unroll
    for (int i = 0; i < 4; i++) {
        int r = ty * 4 + i;
        float inv = 1.0f / l_s[r];
        float4 v = make_float4(acc[i][0] * inv, acc[i][1] * inv,
                               acc[i][2] * inv, acc[i][3] * inv);
        *(float4*)&g_AO[((size_t)(b * SEQ + q0 + r)) * EMB + h * HD + tx * 4] = v;
    }
}

// ---------------------------------------------------------------------------

extern "C" void kernel_launch(void* const* d_in, const int* in_sizes, int n_in,
                              void* d_out, int out_size)
{
    const float* x  = (const float*)d_in[0];
    const float* WQ = (const float*)d_in[1];
    const float* WK = (const float*)d_in[2];
    const float* WV = (const float*)d_in[3];
    const float* WO = (const float*)d_in[4];
    // d_in[5] = mask (int32 tril) — causal, applied analytically in-kernel.
    float* out = (float*)d_out;

    const int SMEM_ATTN = (4 * 64 * 68 + 3 * 64) * (int)sizeof(float); // 70400 B
    cudaFuncSetAttribute(attn_kernel,
                         cudaFuncAttributeMaxDynamicSharedMemorySize, SMEM_ATTN);

    dim3 gg(EMB / 64, MROWS / 64);   // (8, 128)

    // Q, K, V projections
    gemm_nt<<<gg, 256>>>(x, WQ, nullptr, 0);
    gemm_nt<<<gg, 256>>>(x, WK, nullptr, 1);
    gemm_nt<<<gg, 256>>>(x, WV, nullptr, 2);

    // flash attention: 32 (b,h) x 32 q-tiles
    attn_kernel<<<dim3(BATCH * NH, SEQ / 64), 256, SMEM_ATTN>>>();

    // output projection (A=nullptr -> reads g_AO)
    gemm_nt<<<gg, 256>>>(nullptr, WO, out, 3);
}